// round 13
// baseline (speedup 1.0000x reference)
#include <cuda_runtime.h>
#include <cuda_bf16.h>

// SoftPool2d: x (16, 96, 256, 256) f32, 2x2 window, stride 2, no pad.
// out (16, 96, 128, 128) f32.
//
// Pure streaming (no reuse): read 402.7MB + write 100.7MB -> HBM-bound.
// R12 (champion config, pinned): 4 outputs/thread. 2x float4 loads per input
// row x 2 rows (MLP_p1=4), one float4 store. __launch_bounds__(256, 8) pins
// regs<=32 so 8 CTAs/SM (2048 thr) always fit: measured invariant is
// outstanding-loads/SM = warps x MLP ~ 212, and MLP4 @ full occupancy is the
// best point on that curve (R3: 86.1% DRAM, 6.82 TB/s). MLP8 @ half occupancy
// (R10) gave the same product and slightly worse DRAM%.

#define H 256
#define W 256
#define HO 128
#define WO 128

// quads of output pixels: (B*C) * HO * (WO/4) = 1536 * 128 * 32
#define NQUAD (16 * 96 * 128 * 32)

__device__ __forceinline__ float softpool4(float t0, float t1, float t2, float t3) {
    float m = fmaxf(fmaxf(t0, t1), fmaxf(t2, t3));
    float e0 = __expf(t0 - m);
    float e1 = __expf(t1 - m);
    float e2 = __expf(t2 - m);
    float e3 = __expf(t3 - m);
    float num = fmaf(t0, e0, fmaf(t1, e1, fmaf(t2, e2, t3 * e3)));
    float den = e0 + e1 + e2 + e3;
    return num * __fdividef(1.0f, den);
}

__global__ __launch_bounds__(256, 8) void SoftPool2d_850403524762_kernel(
    const float* __restrict__ x, float* __restrict__ out) {
    int idx = blockIdx.x * blockDim.x + threadIdx.x;
    if (idx >= NQUAD) return;

    int wg = idx & 31;          // which 8-col group along W (32 groups)
    int ho = (idx >> 5) & 127;  // output row
    int bc = idx >> 12;         // fused batch*channel plane

    // input rows 2*ho and 2*ho+1 of plane bc; 8 input cols -> 2 float4 per row
    const float4* r0 = (const float4*)(x + (size_t)bc * (H * W) + (size_t)(2 * ho) * W) + 2 * wg;
    const float4* r1 = r0 + (W / 4);

    // 4 independent streaming loads, front-batched
    float4 a0 = __ldcs(r0 + 0);
    float4 a1 = __ldcs(r0 + 1);
    float4 b0 = __ldcs(r1 + 0);
    float4 b1 = __ldcs(r1 + 1);

    float4 o;
    o.x = softpool4(a0.x, a0.y, b0.x, b0.y);
    o.y = softpool4(a0.z, a0.w, b0.z, b0.w);
    o.z = softpool4(a1.x, a1.y, b1.x, b1.y);
    o.w = softpool4(a1.z, a1.w, b1.z, b1.w);

    float4* orow = (float4*)(out + (size_t)bc * (HO * WO) + (size_t)ho * WO) + wg;
    __stcs(orow, o);
}

extern "C" void kernel_launch(void* const* d_in, const int* in_sizes, int n_in,
                              void* d_out, int out_size) {
    const float* x = (const float*)d_in[0];
    float* out = (float*)d_out;
    const int threads = 256;
    const int blocks = (NQUAD + threads - 1) / threads;  // 24576
    SoftPool2d_850403524762_kernel<<<blocks, threads>>>(x, out);
}

// round 14
// speedup vs baseline: 1.0039x; 1.0039x over previous
#include <cuda_runtime.h>
#include <cuda_bf16.h>

// SoftPool2d: x (16, 96, 256, 256) f32, 2x2 window, stride 2, no pad.
// out (16, 96, 128, 128) f32.
//
// Pure streaming (no reuse): read 402.7MB + write 100.7MB -> HBM-bound.
// R13: warp-strided load tiling. Previous champion had thread i loading
// adjacent float4 pairs (r0[2i], r0[2i+1]) -> each LDG.128 had lanes at 32B
// stride touching 16B each: every sector half-used per instruction, fetched
// twice through L1tex. Now thread i loads r0[i] and r0[i+32]: each LDG.128 is
// fully dense (512B contiguous per warp, all sectors fully used, one fetch).
// One warp = one input row pair (64 float4/row = 2 dense LDG groups).
// MLP_p1=4 and full occupancy retained (launch_bounds(256,8), regs<=32).

#define H 256
#define W 256
#define HO 128
#define WO 128

#define BC 1536           // B*C planes
#define NWARP (BC * 128)  // one warp per (plane, output row)

__device__ __forceinline__ float softpool4(float t0, float t1, float t2, float t3) {
    float m = fmaxf(fmaxf(t0, t1), fmaxf(t2, t3));
    float e0 = __expf(t0 - m);
    float e1 = __expf(t1 - m);
    float e2 = __expf(t2 - m);
    float e3 = __expf(t3 - m);
    float num = fmaf(t0, e0, fmaf(t1, e1, fmaf(t2, e2, t3 * e3)));
    float den = e0 + e1 + e2 + e3;
    return num * __fdividef(1.0f, den);
}

__global__ __launch_bounds__(256, 8) void SoftPool2d_850403524762_kernel(
    const float* __restrict__ x, float* __restrict__ out) {
    int lane = threadIdx.x & 31;
    int gw = blockIdx.x * 8 + (threadIdx.x >> 5);  // global warp id

    int ho = gw & 127;   // output row
    int bc = gw >> 7;    // fused batch*channel plane

    // input rows 2*ho and 2*ho+1 of plane bc (each row = 64 float4)
    const float4* r0 = (const float4*)(x + (size_t)bc * (H * W) + (size_t)(2 * ho) * W);
    const float4* r1 = r0 + (W / 4);

    // 4 independent, fully-dense streaming loads (warp covers 512B per LDG)
    float4 a0 = __ldcs(r0 + lane);
    float4 a1 = __ldcs(r0 + lane + 32);
    float4 b0 = __ldcs(r1 + lane);
    float4 b1 = __ldcs(r1 + lane + 32);

    // a0/b0 cover input cols [4*lane, 4*lane+4) -> output cols 2*lane, 2*lane+1
    // a1/b1 cover input cols 128 + [4*lane, ...) -> output cols 64 + 2*lane, +1
    float2 o0, o1;
    o0.x = softpool4(a0.x, a0.y, b0.x, b0.y);
    o0.y = softpool4(a0.z, a0.w, b0.z, b0.w);
    o1.x = softpool4(a1.x, a1.y, b1.x, b1.y);
    o1.y = softpool4(a1.z, a1.w, b1.z, b1.w);

    float2* orow = (float2*)(out + (size_t)bc * (HO * WO) + (size_t)ho * WO);
    __stcs(orow + lane, o0);
    __stcs(orow + lane + 32, o1);
}

extern "C" void kernel_launch(void* const* d_in, const int* in_sizes, int n_in,
                              void* d_out, int out_size) {
    const float* x = (const float*)d_in[0];
    float* out = (float*)d_out;
    const int threads = 256;                 // 8 warps/block
    const int blocks = NWARP / 8;            // 24576
    SoftPool2d_850403524762_kernel<<<blocks, threads>>>(x, out);
}